// round 2
// baseline (speedup 1.0000x reference)
#include <cuda_runtime.h>
#include <cstdint>

// ---------------- problem constants ----------------
#define Bn   32
#define Tn   3000
#define Cn   512
#define KKn  2560                 // Cin * ksize = 512*5
#define Tp   3136                 // padded time length for transposed input
#define BTn  (Bn*Tn)              // 96000
#define NTT  24                   // ceil(3000/128)
#define CS_SZ   (BTn*Cn)          // 49,152,000
#define MASK_OFF CS_SZ
#define LOSS_OFF (CS_SZ + BTn)

// ---------------- scratch (device globals; no allocations allowed) ----------
__device__ float g_ht[(size_t)Bn * Cn * Tp];   // transposed, padded input [b][c][t+2]
__device__ float g_part[4 * BTn];              // partial logits per 128-co block
__device__ float g_alpha[BTn];
__device__ float g_w1[BTn];
__device__ float g_w2[BTn];
__device__ int   g_fpos[BTn];                  // fire positions per batch
__device__ int   g_nfire[Bn];
__device__ int   g_tail[Bn];
__device__ float g_bsum[Bn];

// ---------------- f32x2 helpers (sm_100+: packed fp32 FMA, PTX-only) -------
__device__ __forceinline__ void ffma2(unsigned long long& d,
                                      unsigned long long a,
                                      unsigned long long b) {
    asm("fma.rn.f32x2 %0, %1, %2, %0;" : "+l"(d) : "l"(a), "l"(b));
}
__device__ __forceinline__ unsigned long long pk2(float x) {
    unsigned long long r;
    asm("mov.b64 %0, {%1, %1};" : "=l"(r) : "f"(x));
    return r;
}
__device__ __forceinline__ void unpk(float& lo, float& hi, unsigned long long v) {
    asm("mov.b64 {%0, %1}, %2;" : "=f"(lo), "=f"(hi) : "l"(v));
}

// ---------------- 0) zero the pad regions of g_ht ---------------------------
__global__ void pad_zero_k() {
    int idx = blockIdx.x * blockDim.x + threadIdx.x;
    const int npad = 136;                       // t in {0,1} U [3002,3136)
    int total = Bn * Cn * npad;
    if (idx >= total) return;
    int pi  = idx % npad;
    int rem = idx / npad;
    int c = rem % Cn;
    int b = rem / Cn;
    int t = (pi < 2) ? pi : (pi + 3000);        // 3002..3135
    g_ht[((size_t)b * Cn + c) * Tp + t] = 0.0f;
}

// ---------------- 1) transpose hs_pad [B,T,C] -> g_ht [B,C,Tp] (offset +2) --
__global__ void transpose_k(const float* __restrict__ hs) {
    __shared__ float tile[32][33];
    int b  = blockIdx.z;
    int t0 = blockIdx.y * 32;
    int c0 = blockIdx.x * 32;
    int tx = threadIdx.x, ty = threadIdx.y;     // block (32,8)
#pragma unroll
    for (int i = 0; i < 4; i++) {
        int t = t0 + ty + i * 8;
        float v = 0.0f;
        if (t < Tn) v = hs[((size_t)b * Tn + t) * Cn + (c0 + tx)];
        tile[ty + i * 8][tx] = v;
    }
    __syncthreads();
#pragma unroll
    for (int i = 0; i < 4; i++) {
        int c = c0 + ty + i * 8;
        int t = t0 + tx;
        if (t < Tn)
            g_ht[((size_t)b * Cn + c) * Tp + 2 + t] = tile[tx][ty + i * 8];
    }
}

// ---------------- 2) conv-as-GEMM + relu + linear partial reduction ---------
// A = conv_w viewed as [512 co][2560 kk] (row-major contiguous!)
// B[kk][t]  = g_ht[b][kk/5][t0 + t + kk%5]
// Block: 128 co x 128 t, K-chunks of 16, 256 threads, 8x8 microtile (f32x2).
__global__ void __launch_bounds__(256)
conv_gemm_k(const float* __restrict__ convw,
            const float* __restrict__ convb,
            const float* __restrict__ linw) {
    __shared__ __align__(16) float As[16][132];
    __shared__ __align__(16) float Bs[16][128];

    const int tid = threadIdx.x;
    const int b   = blockIdx.x / NTT;
    const int tt  = blockIdx.x % NTT;
    const int cb  = blockIdx.y;
    const int t0  = tt * 128;
    const int co0 = cb * 128;
    const int ty  = tid >> 4, tx = tid & 15;
    const int ty8 = ty * 8,  tx8 = tx * 8;
    const float* htb = g_ht + (size_t)b * Cn * Tp;

    unsigned long long acc[8][4];
#pragma unroll
    for (int i = 0; i < 8; i++)
#pragma unroll
        for (int j = 0; j < 4; j++) acc[i][j] = 0ull;

    // prime chunk 0
#pragma unroll
    for (int i = 0; i < 8; i++) {
        int e = tid + i * 256;
        As[e & 15][e >> 4] = convw[(co0 + (e >> 4)) * KKn + (e & 15)];
    }
#pragma unroll
    for (int i = 0; i < 8; i++) {
        int e = tid + i * 256;
        int r = e >> 7, t = e & 127;
        int kk = r;
        int ci = kk / 5, kr = kk - ci * 5;
        Bs[r][t] = htb[ci * Tp + t0 + t + kr];
    }
    __syncthreads();

    const int NCHUNK = KKn / 16;                // 160
    for (int ck = 0; ck < NCHUNK; ck++) {
        float ra[8], rb[8];
        if (ck + 1 < NCHUNK) {
            int kk0 = (ck + 1) * 16;
#pragma unroll
            for (int i = 0; i < 8; i++) {
                int e = tid + i * 256;
                ra[i] = convw[(co0 + (e >> 4)) * KKn + kk0 + (e & 15)];
            }
#pragma unroll
            for (int i = 0; i < 8; i++) {
                int e = tid + i * 256;
                int r = e >> 7, t = e & 127;
                int kk = kk0 + r;
                int ci = kk / 5, kr = kk - ci * 5;
                rb[i] = htb[ci * Tp + t0 + t + kr];
            }
        }
        // compute current chunk
#pragma unroll
        for (int kq = 0; kq < 16; kq++) {
            float4 av0 = *reinterpret_cast<const float4*>(&As[kq][ty8]);
            float4 av1 = *reinterpret_cast<const float4*>(&As[kq][ty8 + 4]);
            const unsigned long long* bp =
                reinterpret_cast<const unsigned long long*>(&Bs[kq][tx8]);
            unsigned long long b0 = bp[0], b1 = bp[1], b2 = bp[2], b3 = bp[3];
            float aarr[8] = {av0.x, av0.y, av0.z, av0.w,
                             av1.x, av1.y, av1.z, av1.w};
#pragma unroll
            for (int i = 0; i < 8; i++) {
                unsigned long long ad = pk2(aarr[i]);
                ffma2(acc[i][0], ad, b0);
                ffma2(acc[i][1], ad, b1);
                ffma2(acc[i][2], ad, b2);
                ffma2(acc[i][3], ad, b3);
            }
        }
        __syncthreads();
        if (ck + 1 < NCHUNK) {
#pragma unroll
            for (int i = 0; i < 8; i++) {
                int e = tid + i * 256;
                As[e & 15][e >> 4] = ra[i];
            }
#pragma unroll
            for (int i = 0; i < 8; i++) {
                int e = tid + i * 256;
                Bs[e >> 7][e & 127] = rb[i];
            }
            __syncthreads();
        }
    }

    // epilogue: relu(x+bias) * lin_w, reduce over the 128 co of this block
    float bias_r[8], lw_r[8];
#pragma unroll
    for (int i = 0; i < 8; i++) {
        bias_r[i] = convb[co0 + ty8 + i];
        lw_r[i]   = linw[co0 + ty8 + i];
    }
    float ps[8] = {0, 0, 0, 0, 0, 0, 0, 0};
#pragma unroll
    for (int i = 0; i < 8; i++) {
#pragma unroll
        for (int jp = 0; jp < 4; jp++) {
            float x0, x1;
            unpk(x0, x1, acc[i][jp]);
            x0 += bias_r[i]; x1 += bias_r[i];
            x0 = x0 > 0.f ? x0 : 0.f;
            x1 = x1 > 0.f ? x1 : 0.f;
            ps[2 * jp]     = fmaf(lw_r[i], x0, ps[2 * jp]);
            ps[2 * jp + 1] = fmaf(lw_r[i], x1, ps[2 * jp + 1]);
        }
    }
    __syncthreads();
    float* red = &As[0][0];                     // reuse smem (2112 >= 2048 floats)
#pragma unroll
    for (int j = 0; j < 8; j++) red[ty * 128 + tx8 + j] = ps[j];
    __syncthreads();
    if (tid < 128) {
        float s = 0.f;
#pragma unroll
        for (int r = 0; r < 16; r++) s += red[r * 128 + tid];
        int t = t0 + tid;
        if (t < Tn) g_part[cb * BTn + b * Tn + t] = s;
    }
}

// ---------------- 3) alpha = sigmoid(sum of 4 partials + lin_b) -------------
__global__ void alpha_k(const float* __restrict__ linb) {
    int idx = blockIdx.x * blockDim.x + threadIdx.x;
    if (idx >= BTn) return;
    float l = g_part[idx] + g_part[BTn + idx] + g_part[2 * BTn + idx] +
              g_part[3 * BTn + idx] + linb[0];
    g_alpha[idx] = 1.0f / (1.0f + expf(-l));
}

// ---------------- 4) loss_pen = sum_b |sum_t alpha| --------------------------
__global__ void loss_a_k() {
    int b = blockIdx.x;
    __shared__ float sm[256];
    float s = 0.f;
    for (int t = threadIdx.x; t < Tn; t += 256) s += g_alpha[b * Tn + t];
    sm[threadIdx.x] = s;
    __syncthreads();
    for (int st = 128; st > 0; st >>= 1) {
        if (threadIdx.x < st) sm[threadIdx.x] += sm[threadIdx.x + st];
        __syncthreads();
    }
    if (threadIdx.x == 0) g_bsum[b] = sm[0];
}
__global__ void loss_b_k(float* out, int out_size) {
    if ((long long)out_size > LOSS_OFF) {
        float s = 0.f;
        for (int b = 0; b < Bn; b++) s += fabsf(g_bsum[b]);
        out[LOSS_OFF] = s;
    }
}

// ---------------- 5) scalar CIF scan (one warp per sequence) ----------------
// Replicates reference f32 ops exactly: acc2=acc+a; fired=acc2>=1; a1=1-acc;
// weights: fired -> (a1 to row F-1, a-a1 to row F); else a to row F.
__global__ void scan_k(const int* __restrict__ msk) {
    int b = blockIdx.x;
    int lane = threadIdx.x;
    float acc = 0.0f;
    int nfire = 0;
    for (int t0 = 0; t0 < Tn; t0 += 32) {
        int t = t0 + lane;
        float a = 0.f;
        if (t < Tn) {
            a = g_alpha[b * Tn + t];
            if (msk[b * Tn + t] == 0) a = 0.f;
        }
        int n = min(32, Tn - t0);
        float w1 = 0.f, w2 = 0.f;
        for (int i = 0; i < n; i++) {
            float ai = __shfl_sync(0xffffffffu, a, i);
            float acc2 = acc + ai;
            bool fired = (acc2 >= 1.0f);
            float a1 = 1.0f - acc;
            if (lane == i) {
                if (fired) { w1 = a1; w2 = ai - a1; }
                else       { w1 = ai; w2 = 0.f; }
            }
            if (fired) {
                if (lane == i) g_fpos[b * Tn + nfire] = t0 + i;
                nfire++;
                acc = ai - a1;
            } else {
                acc = acc2;
            }
        }
        if (t < Tn) { g_w1[b * Tn + t] = w1; g_w2[b * Tn + t] = w2; }
    }
    if (lane == 0) {
        g_nfire[b] = nfire;
        g_tail[b]  = (acc >= 0.5f) ? 1 : 0;
    }
}

// ---------------- 6) parallel emission: row j gathers its t-segment ---------
__global__ void emit_k(const float* __restrict__ hs, float* __restrict__ out,
                       int out_size) {
    int row = blockIdx.x;               // = b*T + j
    int b = row / Tn;
    int j = row % Tn;
    int nf = g_nfire[b];
    int nr = nf + g_tail[b];
    float4 accv = make_float4(0.f, 0.f, 0.f, 0.f);
    int c4 = threadIdx.x;               // 128 threads * float4 = 512 channels
    const float4* hb = reinterpret_cast<const float4*>(hs) + (size_t)b * Tn * 128;
    if (j < nr) {
        int s = (j == 0) ? 0 : g_fpos[b * Tn + j - 1];
        int e = (j < nf) ? g_fpos[b * Tn + j] : (Tn - 1);
        for (int t = s; t <= e; t++) {
            float w = (t == s && j > 0) ? g_w2[b * Tn + t] : g_w1[b * Tn + t];
            float4 h = hb[(size_t)t * 128 + c4];
            accv.x = fmaf(w, h.x, accv.x);
            accv.y = fmaf(w, h.y, accv.y);
            accv.z = fmaf(w, h.z, accv.z);
            accv.w = fmaf(w, h.w, accv.w);
        }
    }
    reinterpret_cast<float4*>(out)[(size_t)row * 128 + c4] = accv;

    // cs_mask[b,0,j] = any(cs[b,j,:] != 0)
    int nz = (accv.x != 0.f) | (accv.y != 0.f) | (accv.z != 0.f) | (accv.w != 0.f);
    __shared__ int s_any[4];
    unsigned bal = __ballot_sync(0xffffffffu, nz);
    if ((threadIdx.x & 31) == 0) s_any[threadIdx.x >> 5] = (bal != 0u);
    __syncthreads();
    if (threadIdx.x == 0) {
        int any = s_any[0] | s_any[1] | s_any[2] | s_any[3];
        if ((long long)out_size >= (long long)MASK_OFF + BTn)
            out[MASK_OFF + row] = any ? 1.0f : 0.0f;
    }
}

// ---------------- launcher ---------------------------------------------------
extern "C" void kernel_launch(void* const* d_in, const int* in_sizes, int n_in,
                              void* d_out, int out_size) {
    const float* hs   = (const float*)d_in[0];   // hs_pad  [B,T,C] f32
    const int*   msk  = (const int*)  d_in[1];   // hs_mask [B,1,T] i32
    const float* cw   = (const float*)d_in[2];   // conv_w  [C,C,5]
    const float* cb   = (const float*)d_in[3];   // conv_b  [C]
    const float* lw   = (const float*)d_in[4];   // lin_w   [C,1]
    const float* lb   = (const float*)d_in[5];   // lin_b   [1]
    float* out = (float*)d_out;

    pad_zero_k<<<(Bn * Cn * 136 + 255) / 256, 256>>>();
    transpose_k<<<dim3(Cn / 32, (Tn + 31) / 32, Bn), dim3(32, 8)>>>(hs);
    conv_gemm_k<<<dim3(NTT * Bn, 4), 256>>>(cw, cb, lw);
    alpha_k<<<(BTn + 255) / 256, 256>>>(lb);
    loss_a_k<<<Bn, 256>>>();
    loss_b_k<<<1, 1>>>(out, out_size);
    scan_k<<<Bn, 32>>>(msk);
    emit_k<<<BTn, 128>>>(hs, out, out_size);
}